// round 8
// baseline (speedup 1.0000x reference)
#include <cuda_runtime.h>
#include <cuda_fp16.h>
#include <cstdint>

typedef uint32_t u32;

#define A_TOT  256
#define D_IN   39
#define H      50
#define BLK    128
#define TPB    4            // row-tiles of 128 per block
#define S1I    48           // interleaved B1 row stride (words); phase covers all 32 banks
#define S2I    80           // interleaved B2 row stride (words)
#define XSTR   40           // x-stage row stride in floats (conflict-free LDS.64)

// dynamic smem layout (bytes)
#define OFF_B1   0
#define OFF_B2   10752
#define OFF_X    28672                    // 4 warps x 1280 floats; unioned with raw-weight scratch
#define OFF_BIAS 49152
#define SMEM_BYTES 49920

__device__ __forceinline__ u32 pack_h2(float a, float b) {
    __half2 h = __floats2half2_rn(a, b);
    return *reinterpret_cast<u32*>(&h);
}
__device__ __forceinline__ u32 h2mul(u32 a, u32 b) {
    __half2 r = __hmul2(*reinterpret_cast<__half2*>(&a), *reinterpret_cast<__half2*>(&b));
    return *reinterpret_cast<u32*>(&r);
}
__device__ __forceinline__ u32 h2add(u32 a, u32 b) {
    __half2 r = __hadd2(*reinterpret_cast<__half2*>(&a), *reinterpret_cast<__half2*>(&b));
    return *reinterpret_cast<u32*>(&r);
}
__device__ __forceinline__ u32 h2tanh(u32 a) {
    u32 d; asm("tanh.approx.f16x2 %0, %1;" : "=r"(d) : "r"(a)); return d;
}
// silu(v) = (v/2)*(1+tanh(v/2)) with hv = pack(v0/2, v1/2)
__device__ __forceinline__ u32 silu_h2_prescaled(u32 hv) {
    const u32 one2 = 0x3C003C00u;
    return h2mul(hv, h2add(one2, h2tanh(hv)));
}
__device__ __forceinline__ void wsplit2(float v0, float v1, u32& hw, u32& lw) {
    float h0 = __half2float(__float2half_rn(v0));
    float h1 = __half2float(__float2half_rn(v1));
    hw = pack_h2(h0, h1);
    lw = pack_h2(v0 - h0, v1 - h1);
}

#define MMA(Cb, A0, A1, A2, A3, B0, B1)                                  \
    asm volatile("mma.sync.aligned.m16n8k16.row.col.f32.f16.f16.f32 "    \
                 "{%0,%1,%2,%3}, {%4,%5,%6,%7}, {%8,%9}, {%0,%1,%2,%3};" \
                 : "+f"(Cb[0]), "+f"(Cb[1]), "+f"(Cb[2]), "+f"(Cb[3])    \
                 : "r"(A0), "r"(A1), "r"(A2), "r"(A3), "r"(B0), "r"(B1))

// stage 32 rows (this warp's) of desc into warp-private smem, coalesced
__device__ __forceinline__ void stage_x(float* __restrict__ xw,
                                        const float* __restrict__ descw,
                                        size_t rs, int lid)
{
    #pragma unroll
    for (int j = 0; j < 40; j++) {
        int idx = j * 32 + lid;            // 0..1279
        int r = idx / XSTR, c = idx - r * XSTR;
        float v = (c < D_IN) ? descw[(size_t)r * rs + c] : 0.0f;
        xw[idx] = v;
    }
}

__global__ __launch_bounds__(BLK, 4)
void atomic_mlp_mma5(const float* __restrict__ desc,
                     const int*   __restrict__ numbers,
                     const float* __restrict__ W1, const float* __restrict__ b1,
                     const float* __restrict__ W2, const float* __restrict__ b2,
                     const float* __restrict__ W3, const float* __restrict__ b3,
                     float* __restrict__ out)
{
    extern __shared__ __align__(16) char dsm[];
    u32*   sB1  = (u32*)(dsm + OFF_B1);
    u32*   sB2  = (u32*)(dsm + OFF_B2);
    float* sx   = (float*)(dsm + OFF_X);
    float* sraw = (float*)(dsm + OFF_X);       // union: raw weights live only in prologue
    float* b1h  = (float*)(dsm + OFF_BIAS);
    float* b2h  = b1h + 56;
    float* w3v  = b2h + 56;
    float* b3s  = w3v + 56;

    const int t   = threadIdx.x;
    const int wid = t >> 5;
    const int lid = t & 31;
    const int g   = lid >> 2;
    const int tq  = lid & 3;
    const int a   = blockIdx.x;
    const int s   = numbers[a];

    const size_t rs   = (size_t)A_TOT * D_IN;
    const size_t acol = (size_t)a * D_IN;

    // ---- prologue: raw weights -> smem (coalesced) ----
    #pragma unroll
    for (int j = 0; j < 16; j++) {
        int i = t + j * BLK;
        if (i < D_IN * H) sraw[i] = W1[s * D_IN * H + i];
    }
    #pragma unroll
    for (int j = 0; j < 20; j++) {
        int i = t + j * BLK;
        if (i < H * H) sraw[D_IN * H + i] = W2[s * H * H + i];
    }
    if (t < 56) {
        b1h[t] = (t < H) ? 0.5f * b1[s * H + t] : 0.0f;
        b2h[t] = (t < H) ? 0.5f * b2[s * H + t] : 0.0f;
        w3v[t] = (t < H) ? W3[s * H + t] : 0.0f;
    }
    if (t == 0) b3s[0] = b3[s];
    __syncthreads();

    // ---- build split-transposed, interleaved weight tiles ----
    #pragma unroll
    for (int j = 0; j < 11; j++) {
        int i = t + j * BLK;
        if (i < 56 * 24) {
            int n = i / 24, w = i % 24, k0 = 2 * w;
            float v0 = (k0     < D_IN && n < H) ? sraw[k0 * H + n]       : 0.0f;
            float v1 = (k0 + 1 < D_IN && n < H) ? sraw[(k0 + 1) * H + n] : 0.0f;
            u32 hw, lw; wsplit2(v0, v1, hw, lw);
            int kk = w >> 3, jj = w & 7;
            int p = n * S1I + kk * 16 + (jj & 3) * 4 + (jj >> 2);
            sB1[p]     = hw;
            sB1[p + 2] = lw;
        }
    }
    #pragma unroll
    for (int j = 0; j < 14; j++) {
        int i = t + j * BLK;               // exactly 56*32
        int n = i / 32, w = i % 32, k0 = 2 * w;
        float v0 = (k0     < H && n < H) ? sraw[D_IN * H + k0 * H + n]       : 0.0f;
        float v1 = (k0 + 1 < H && n < H) ? sraw[D_IN * H + (k0 + 1) * H + n] : 0.0f;
        u32 hw, lw; wsplit2(v0, v1, hw, lw);
        int kk = w >> 3, jj = w & 7;
        int p = n * S2I + kk * 16 + (jj & 3) * 4 + (jj >> 2);
        sB2[p]     = hw;
        sB2[p + 2] = lw;
    }
    __syncthreads();                        // sraw dead from here; sx reusable

    float* xw = sx + wid * (32 * XSTR);

    // ---- stage tile 0's rows for this warp ----
    stage_x(xw, desc + ((size_t)(blockIdx.y * TPB * 128) + wid * 32) * rs + acol, rs, lid);
    __syncwarp();

    // ================= tile loop (no block barriers) =================
    #pragma unroll 1
    for (int it = 0; it < TPB; it++) {
        // ---- extract layer-1 A fragments from x-stage (LDS.64 + fp16 pack) ----
        u32 ah[3][2][4];
        #pragma unroll
        for (int kk = 0; kk < 3; kk++)
            #pragma unroll
            for (int q = 0; q < 4; q++) {
                int rl = (q >> 1) * 16 + (q & 1) * 8 + g;
                int m = q >> 1, o = q & 1;
                float2 v0 = *reinterpret_cast<const float2*>(xw + rl * XSTR + kk * 16 + 2 * tq);
                ah[kk][m][o] = pack_h2(v0.x, v0.y);
                if (kk < 2) {
                    float2 v1 = *reinterpret_cast<const float2*>(xw + rl * XSTR + kk * 16 + 8 + 2 * tq);
                    ah[kk][m][2 + o] = pack_h2(v1.x, v1.y);
                } else {
                    ah[kk][m][2 + o] = 0u;   // cols 40..47 are K-pad
                }
            }
        // NOTE: kk=2 first half covers cols 32..39; col 39 staged as 0, B rows 39+ zero.

        // ---- layer 1: C += Ahi*(Bhi + Blo) ----
        float c[56];
        #pragma unroll
        for (int i = 0; i < 56; i++) c[i] = 0.0f;

        #pragma unroll
        for (int kk = 0; kk < 3; kk++)
            #pragma unroll
            for (int n = 0; n < 7; n++) {
                const uint4 b = *reinterpret_cast<const uint4*>(
                    &sB1[(n * 8 + g) * S1I + kk * 16 + 4 * tq]);
                #pragma unroll
                for (int m = 0; m < 2; m++) {
                    float* C = &c[(m * 7 + n) * 4];
                    MMA(C, ah[kk][m][0], ah[kk][m][1], ah[kk][m][2], ah[kk][m][3], b.x, b.y);
                    MMA(C, ah[kk][m][0], ah[kk][m][1], ah[kk][m][2], ah[kk][m][3], b.z, b.w);
                }
            }

        // ---- epilogue 1: h = silu(c + b1) (packed tanh) -> fp16 A2 frags ----
        u32 ch0[14], ch1[14];
        #pragma unroll
        for (int m = 0; m < 2; m++)
            #pragma unroll
            for (int n = 0; n < 7; n++) {
                int col = n * 8 + 2 * tq;
                float bi0 = b1h[col], bi1 = b1h[col + 1];
                int idx = (m * 7 + n) * 4;
                ch0[m * 7 + n] = silu_h2_prescaled(
                    pack_h2(fmaf(0.5f, c[idx],     bi0), fmaf(0.5f, c[idx + 1], bi1)));
                ch1[m * 7 + n] = silu_h2_prescaled(
                    pack_h2(fmaf(0.5f, c[idx + 2], bi0), fmaf(0.5f, c[idx + 3], bi1)));
            }

        // ---- restage next tile (hidden behind layer-2 MMAs) ----
        __syncwarp();                       // all lanes done reading this tile's x
        if (it + 1 < TPB) {
            stage_x(xw, desc + ((size_t)((blockIdx.y * TPB + it + 1) * 128) + wid * 32) * rs + acol,
                    rs, lid);
        }
        __syncwarp();                       // STS visible to cross-lane LDS next iteration

        // ---- layer 2: C2 += h*(B2hi + B2lo), K=64 (kk=3 upper half zero) ----
        float c2[56];
        #pragma unroll
        for (int i = 0; i < 56; i++) c2[i] = 0.0f;

        #pragma unroll
        for (int kk = 0; kk < 4; kk++) {
            u32 a0[2], a1[2], a2[2], a3[2];
            #pragma unroll
            for (int m = 0; m < 2; m++) {
                a0[m] = ch0[m * 7 + 2 * kk];
                a1[m] = ch1[m * 7 + 2 * kk];
                if (kk < 3) {
                    a2[m] = ch0[m * 7 + 2 * kk + 1];
                    a3[m] = ch1[m * 7 + 2 * kk + 1];
                } else {
                    a2[m] = 0u; a3[m] = 0u;
                }
            }
            #pragma unroll
            for (int n = 0; n < 7; n++) {
                const uint4 b = *reinterpret_cast<const uint4*>(
                    &sB2[(n * 8 + g) * S2I + kk * 16 + 4 * tq]);
                #pragma unroll
                for (int m = 0; m < 2; m++) {
                    float* C = &c2[(m * 7 + n) * 4];
                    MMA(C, a0[m], a1[m], a2[m], a3[m], b.x, b.y);
                    MMA(C, a0[m], a1[m], a2[m], a3[m], b.z, b.w);
                }
            }
        }

        // ---- epilogue 2: packed-tanh silu, dot W3 (fp32), reduce, store ----
        float sum[4] = {0.0f, 0.0f, 0.0f, 0.0f};
        #pragma unroll
        for (int m = 0; m < 2; m++)
            #pragma unroll
            for (int n = 0; n < 7; n++) {
                int col = n * 8 + 2 * tq;
                float bi0 = b2h[col], bi1 = b2h[col + 1];
                float w30 = w3v[col], w31 = w3v[col + 1];
                int idx = (m * 7 + n) * 4;
                u32 h0 = silu_h2_prescaled(
                    pack_h2(fmaf(0.5f, c2[idx],     bi0), fmaf(0.5f, c2[idx + 1], bi1)));
                u32 h1 = silu_h2_prescaled(
                    pack_h2(fmaf(0.5f, c2[idx + 2], bi0), fmaf(0.5f, c2[idx + 3], bi1)));
                __half2 H0 = *reinterpret_cast<__half2*>(&h0);
                __half2 H1 = *reinterpret_cast<__half2*>(&h1);
                sum[m * 2 + 0] += __low2float(H0) * w30 + __high2float(H0) * w31;
                sum[m * 2 + 1] += __low2float(H1) * w30 + __high2float(H1) * w31;
            }
        #pragma unroll
        for (int q = 0; q < 4; q++) {
            sum[q] += __shfl_xor_sync(0xffffffffu, sum[q], 1);
            sum[q] += __shfl_xor_sync(0xffffffffu, sum[q], 2);
        }
        if (tq == 0) {
            const int R0 = (blockIdx.y * TPB + it) * 128 + wid * 32;
            float bb = b3s[0];
            #pragma unroll
            for (int q = 0; q < 4; q++) {
                int r = R0 + (q >> 1) * 16 + (q & 1) * 8 + g;
                out[(size_t)r * A_TOT + a] = sum[q] + bb;
            }
        }
    }
}

extern "C" void kernel_launch(void* const* d_in, const int* in_sizes, int n_in,
                              void* d_out, int out_size)
{
    const float* desc    = (const float*)d_in[0];
    const int*   numbers = (const int*)  d_in[1];
    const float* W1      = (const float*)d_in[2];
    const float* b1      = (const float*)d_in[3];
    const float* W2      = (const float*)d_in[4];
    const float* b2      = (const float*)d_in[5];
    const float* W3      = (const float*)d_in[6];
    const float* b3      = (const float*)d_in[7];
    float* out = (float*)d_out;

    const int N = in_sizes[0] / (A_TOT * D_IN);   // 4096
    static int configured = 0;
    if (!configured) {
        cudaFuncSetAttribute(atomic_mlp_mma5, cudaFuncAttributeMaxDynamicSharedMemorySize, SMEM_BYTES);
        configured = 1;
    }
    dim3 grid(A_TOT, N / (128 * TPB));            // 256 x 8
    atomic_mlp_mma5<<<grid, BLK, SMEM_BYTES>>>(desc, numbers, W1, b1, W2, b2, W3, b3, out);
}

// round 9
// speedup vs baseline: 1.1890x; 1.1890x over previous
#include <cuda_runtime.h>
#include <cuda_fp16.h>
#include <cstdint>

typedef uint32_t u32;

#define A_TOT  256
#define D_IN   39
#define H      50
#define BLK    128
#define TPB    4            // row-tiles of 128 per block
#define S1I    48           // interleaved B1 row stride (words)
#define S2I    80           // interleaved B2 row stride (words)

__device__ __forceinline__ u32 pack_h2(float a, float b) {
    __half2 h = __floats2half2_rn(a, b);
    return *reinterpret_cast<u32*>(&h);
}
__device__ __forceinline__ u32 h2tanh(u32 a) {
    u32 d; asm("tanh.approx.f16x2 %0, %1;" : "=r"(d) : "r"(a)); return d;
}
// packed silu: hv = 0.5*v (half2); returns silu(v) = hv*(1+tanh(hv)) = hfma2(hv,t,hv)
__device__ __forceinline__ u32 silu_from_half(u32 hv) {
    u32 th = h2tanh(hv);
    __half2 r = __hfma2(*reinterpret_cast<__half2*>(&hv),
                        *reinterpret_cast<__half2*>(&th),
                        *reinterpret_cast<__half2*>(&hv));
    return *reinterpret_cast<u32*>(&r);
}
// hv = 0.5*pack(c0,c1) + bias_prepacked(0.5*b)
__device__ __forceinline__ u32 half_bias(float c0, float c1, u32 bp) {
    const u32 h05 = 0x38003800u;
    u32 pc = pack_h2(c0, c1);
    __half2 r = __hfma2(*reinterpret_cast<__half2*>(&pc),
                        *reinterpret_cast<const __half2*>(&h05),
                        *reinterpret_cast<__half2*>(&bp));
    return *reinterpret_cast<u32*>(&r);
}
__device__ __forceinline__ void wsplit2(float v0, float v1, u32& hw, u32& lw) {
    float h0 = __half2float(__float2half_rn(v0));
    float h1 = __half2float(__float2half_rn(v1));
    hw = pack_h2(h0, h1);
    lw = pack_h2(v0 - h0, v1 - h1);
}

#define MMA(Cb, A0, A1, A2, A3, B0, B1)                                  \
    asm volatile("mma.sync.aligned.m16n8k16.row.col.f32.f16.f16.f32 "    \
                 "{%0,%1,%2,%3}, {%4,%5,%6,%7}, {%8,%9}, {%0,%1,%2,%3};" \
                 : "+f"(Cb[0]), "+f"(Cb[1]), "+f"(Cb[2]), "+f"(Cb[3])    \
                 : "r"(A0), "r"(A1), "r"(A2), "r"(A3), "r"(B0), "r"(B1))

#define MMA8(Cb, A0, A1, B0)                                             \
    asm volatile("mma.sync.aligned.m16n8k8.row.col.f32.f16.f16.f32 "     \
                 "{%0,%1,%2,%3}, {%4,%5}, {%6}, {%0,%1,%2,%3};"          \
                 : "+f"(Cb[0]), "+f"(Cb[1]), "+f"(Cb[2]), "+f"(Cb[3])    \
                 : "r"(A0), "r"(A1), "r"(B0))

__global__ __launch_bounds__(BLK, 4)
void atomic_mlp_mma6(const float* __restrict__ desc,
                     const int*   __restrict__ numbers,
                     const float* __restrict__ W1, const float* __restrict__ b1,
                     const float* __restrict__ W2, const float* __restrict__ b2,
                     const float* __restrict__ W3, const float* __restrict__ b3,
                     float* __restrict__ out)
{
    __shared__ __align__(16) u32 sB1[56 * S1I];        // 10752 B (hi/lo interleaved)
    __shared__ __align__(16) u32 sB2[56 * S2I];        // 17920 B
    __shared__ float sraw[D_IN * H + H * H];           // 17800 B
    __shared__ u32 b1p[28], b2p[28];                   // 0.5*bias packed half2 per col-pair
    __shared__ float w3v[56];
    __shared__ float b3s;

    const int t   = threadIdx.x;
    const int wid = t >> 5;
    const int lid = t & 31;
    const int g   = lid >> 2;
    const int tq  = lid & 3;
    const int a   = blockIdx.x;
    const int s   = numbers[a];

    const size_t rs   = (size_t)A_TOT * D_IN;
    const size_t acol = (size_t)a * D_IN;

    // ---- stage raw weights (coalesced, once per block) ----
    #pragma unroll
    for (int j = 0; j < 16; j++) {
        int i = t + j * BLK;
        if (i < D_IN * H) sraw[i] = W1[s * D_IN * H + i];
    }
    #pragma unroll
    for (int j = 0; j < 20; j++) {
        int i = t + j * BLK;
        if (i < H * H) sraw[D_IN * H + i] = W2[s * H * H + i];
    }
    if (t < 28) {
        int c0 = 2 * t, c1 = 2 * t + 1;
        float v0 = (c0 < H) ? 0.5f * b1[s * H + c0] : 0.0f;
        float v1 = (c1 < H) ? 0.5f * b1[s * H + c1] : 0.0f;
        b1p[t] = pack_h2(v0, v1);
        v0 = (c0 < H) ? 0.5f * b2[s * H + c0] : 0.0f;
        v1 = (c1 < H) ? 0.5f * b2[s * H + c1] : 0.0f;
        b2p[t] = pack_h2(v0, v1);
    }
    if (t >= 64 && t < 120) {
        int c = t - 64;
        w3v[c] = (c < H) ? W3[s * H + c] : 0.0f;
    }
    if (t == 0) b3s = b3[s];

    // ---- prefetch tile 0's A fragments, packed fp16 ----
    u32 ahn1[2][2][4];   // kk=0,1 full k16
    u32 ahn2[2][2];      // kk=2 k8 (cols 32..39)
    {
        const int R0 = (blockIdx.y * TPB) * 128 + wid * 32;
        #pragma unroll
        for (int q = 0; q < 4; q++) {
            int r = R0 + (q >> 1) * 16 + (q & 1) * 8 + g;
            const float* rp = desc + (size_t)r * rs + acol;
            int m = q >> 1, o = q & 1;
            ahn1[0][m][o]     = pack_h2(rp[2*tq],      rp[2*tq + 1]);
            ahn1[0][m][2 + o] = pack_h2(rp[8 + 2*tq],  rp[9 + 2*tq]);
            ahn1[1][m][o]     = pack_h2(rp[16 + 2*tq], rp[17 + 2*tq]);
            ahn1[1][m][2 + o] = pack_h2(rp[24 + 2*tq], rp[25 + 2*tq]);
            ahn2[m][o]        = pack_h2(rp[32 + 2*tq], (tq < 3) ? rp[33 + 2*tq] : 0.0f);
        }
    }
    __syncthreads();

    // ---- build split-transposed, interleaved weight tiles ----
    #pragma unroll
    for (int j = 0; j < 11; j++) {
        int i = t + j * BLK;
        if (i < 56 * 24) {
            int n = i / 24, w = i % 24, k0 = 2 * w;
            float v0 = (k0     < D_IN && n < H) ? sraw[k0 * H + n]       : 0.0f;
            float v1 = (k0 + 1 < D_IN && n < H) ? sraw[(k0 + 1) * H + n] : 0.0f;
            u32 hw, lw; wsplit2(v0, v1, hw, lw);
            int kk = w >> 3, jj = w & 7;
            int p = n * S1I + kk * 16 + (jj & 3) * 4 + (jj >> 2);
            sB1[p]     = hw;
            sB1[p + 2] = lw;
        }
    }
    #pragma unroll
    for (int j = 0; j < 14; j++) {
        int i = t + j * BLK;               // exactly 56*32
        int n = i / 32, w = i % 32, k0 = 2 * w;
        float v0 = (k0     < H && n < H) ? sraw[D_IN * H + k0 * H + n]       : 0.0f;
        float v1 = (k0 + 1 < H && n < H) ? sraw[D_IN * H + (k0 + 1) * H + n] : 0.0f;
        u32 hw, lw; wsplit2(v0, v1, hw, lw);
        int kk = w >> 3, jj = w & 7;
        int p = n * S2I + kk * 16 + (jj & 3) * 4 + (jj >> 2);
        sB2[p]     = hw;
        sB2[p + 2] = lw;
    }
    __syncthreads();

    // ================= tile loop (barrier-free body) =================
    #pragma unroll 1
    for (int it = 0; it < TPB; it++) {
        u32 ah1[2][2][4], ah2[2][2];
        #pragma unroll
        for (int kk = 0; kk < 2; kk++)
            #pragma unroll
            for (int m = 0; m < 2; m++)
                #pragma unroll
                for (int o = 0; o < 4; o++)
                    ah1[kk][m][o] = ahn1[kk][m][o];
        #pragma unroll
        for (int m = 0; m < 2; m++) {
            ah2[m][0] = ahn2[m][0];
            ah2[m][1] = ahn2[m][1];
        }

        // ---- layer 1: kk=0,1 k16; kk=2 k8 ----
        float c[56];
        #pragma unroll
        for (int i = 0; i < 56; i++) c[i] = 0.0f;

        #pragma unroll
        for (int kk = 0; kk < 2; kk++)
            #pragma unroll
            for (int n = 0; n < 7; n++) {
                const uint4 b = *reinterpret_cast<const uint4*>(
                    &sB1[(n * 8 + g) * S1I + kk * 16 + 4 * tq]);
                #pragma unroll
                for (int m = 0; m < 2; m++) {
                    float* C = &c[(m * 7 + n) * 4];
                    MMA(C, ah1[kk][m][0], ah1[kk][m][1], ah1[kk][m][2], ah1[kk][m][3], b.x, b.y);
                    MMA(C, ah1[kk][m][0], ah1[kk][m][1], ah1[kk][m][2], ah1[kk][m][3], b.z, b.w);
                }
            }
        #pragma unroll
        for (int n = 0; n < 7; n++) {
            int p = (n * 8 + g) * S1I + 32 + 4 * tq;
            u32 bh = sB1[p], bl = sB1[p + 2];
            #pragma unroll
            for (int m = 0; m < 2; m++) {
                float* C = &c[(m * 7 + n) * 4];
                MMA8(C, ah2[m][0], ah2[m][1], bh);
                MMA8(C, ah2[m][0], ah2[m][1], bl);
            }
        }

        // ---- epilogue 1: packed bias + tanh-silu -> fp16 A2 frags ----
        u32 ch0[14], ch1[14];
        #pragma unroll
        for (int m = 0; m < 2; m++)
            #pragma unroll
            for (int n = 0; n < 7; n++) {
                u32 bp = b1p[n * 4 + tq];
                int idx = (m * 7 + n) * 4;
                ch0[m * 7 + n] = silu_from_half(half_bias(c[idx],     c[idx + 1], bp));
                ch1[m * 7 + n] = silu_from_half(half_bias(c[idx + 2], c[idx + 3], bp));
            }

        // ---- prefetch next tile's A (hidden behind layer-2 MMAs) ----
        if (it + 1 < TPB) {
            const int R0n = (blockIdx.y * TPB + it + 1) * 128 + wid * 32;
            #pragma unroll
            for (int q = 0; q < 4; q++) {
                int r = R0n + (q >> 1) * 16 + (q & 1) * 8 + g;
                const float* rp = desc + (size_t)r * rs + acol;
                int m = q >> 1, o = q & 1;
                ahn1[0][m][o]     = pack_h2(rp[2*tq],      rp[2*tq + 1]);
                ahn1[0][m][2 + o] = pack_h2(rp[8 + 2*tq],  rp[9 + 2*tq]);
                ahn1[1][m][o]     = pack_h2(rp[16 + 2*tq], rp[17 + 2*tq]);
                ahn1[1][m][2 + o] = pack_h2(rp[24 + 2*tq], rp[25 + 2*tq]);
                ahn2[m][o]        = pack_h2(rp[32 + 2*tq], (tq < 3) ? rp[33 + 2*tq] : 0.0f);
            }
        }

        // ---- layer 2: kk=0..2 k16; kk=3 k8 ----
        float c2[56];
        #pragma unroll
        for (int i = 0; i < 56; i++) c2[i] = 0.0f;

        #pragma unroll
        for (int kk = 0; kk < 3; kk++) {
            #pragma unroll
            for (int n = 0; n < 7; n++) {
                const uint4 b = *reinterpret_cast<const uint4*>(
                    &sB2[(n * 8 + g) * S2I + kk * 16 + 4 * tq]);
                #pragma unroll
                for (int m = 0; m < 2; m++) {
                    float* C = &c2[(m * 7 + n) * 4];
                    MMA(C, ch0[m * 7 + 2 * kk], ch1[m * 7 + 2 * kk],
                           ch0[m * 7 + 2 * kk + 1], ch1[m * 7 + 2 * kk + 1], b.x, b.y);
                    MMA(C, ch0[m * 7 + 2 * kk], ch1[m * 7 + 2 * kk],
                           ch0[m * 7 + 2 * kk + 1], ch1[m * 7 + 2 * kk + 1], b.z, b.w);
                }
            }
        }
        #pragma unroll
        for (int n = 0; n < 7; n++) {
            int p = (n * 8 + g) * S2I + 48 + 4 * tq;
            u32 bh = sB2[p], bl = sB2[p + 2];
            #pragma unroll
            for (int m = 0; m < 2; m++) {
                float* C = &c2[(m * 7 + n) * 4];
                MMA8(C, ch0[m * 7 + 6], ch1[m * 7 + 6], bh);
                MMA8(C, ch0[m * 7 + 6], ch1[m * 7 + 6], bl);
            }
        }

        // ---- epilogue 2: packed silu, fp32 dot W3, reduce, store ----
        float sum[4] = {0.0f, 0.0f, 0.0f, 0.0f};
        #pragma unroll
        for (int m = 0; m < 2; m++)
            #pragma unroll
            for (int n = 0; n < 7; n++) {
                u32 bp = b2p[n * 4 + tq];
                int col = n * 8 + 2 * tq;
                float w30 = w3v[col], w31 = w3v[col + 1];
                int idx = (m * 7 + n) * 4;
                u32 s0 = silu_from_half(half_bias(c2[idx],     c2[idx + 1], bp));
                u32 s1 = silu_from_half(half_bias(c2[idx + 2], c2[idx + 3], bp));
                float2 F0 = __half22float2(*reinterpret_cast<__half2*>(&s0));
                float2 F1 = __half22float2(*reinterpret_cast<__half2*>(&s1));
                sum[m * 2 + 0] += F0.x * w30 + F0.y * w31;
                sum[m * 2 + 1] += F1.x * w30 + F1.y * w31;
            }
        #pragma unroll
        for (int q = 0; q < 4; q++) {
            sum[q] += __shfl_xor_sync(0xffffffffu, sum[q], 1);
            sum[q] += __shfl_xor_sync(0xffffffffu, sum[q], 2);
        }
        if (tq == 0) {
            const int R0 = (blockIdx.y * TPB + it) * 128 + wid * 32;
            float bb = b3s;
            #pragma unroll
            for (int q = 0; q < 4; q++) {
                int r = R0 + (q >> 1) * 16 + (q & 1) * 8 + g;
                out[(size_t)r * A_TOT + a] = sum[q] + bb;
            }
        }
    }
}

extern "C" void kernel_launch(void* const* d_in, const int* in_sizes, int n_in,
                              void* d_out, int out_size)
{
    const float* desc    = (const float*)d_in[0];
    const int*   numbers = (const int*)  d_in[1];
    const float* W1      = (const float*)d_in[2];
    const float* b1      = (const float*)d_in[3];
    const float* W2      = (const float*)d_in[4];
    const float* b2      = (const float*)d_in[5];
    const float* W3      = (const float*)d_in[6];
    const float* b3      = (const float*)d_in[7];
    float* out = (float*)d_out;

    const int N = in_sizes[0] / (A_TOT * D_IN);   // 4096
    dim3 grid(A_TOT, N / (128 * TPB));            // 256 x 8
    atomic_mlp_mma6<<<grid, BLK>>>(desc, numbers, W1, b1, W2, b2, W3, b3, out);
}

// round 10
// speedup vs baseline: 1.3128x; 1.1042x over previous
#include <cuda_runtime.h>
#include <cuda_fp16.h>
#include <cstdint>

typedef uint32_t u32;

#define A_TOT  256
#define D_IN   39
#define H      50
#define BLK    128
#define TPB    4            // row-tiles of 128 per block
#define S1I    48           // interleaved B1 row stride (words)
#define S2I    80           // interleaved B2 row stride (words)

__device__ __forceinline__ u32 pack_h2(float a, float b) {
    __half2 h = __floats2half2_rn(a, b);
    return *reinterpret_cast<u32*>(&h);
}
__device__ __forceinline__ u32 h2tanh(u32 a) {
    u32 d; asm("tanh.approx.f16x2 %0, %1;" : "=r"(d) : "r"(a)); return d;
}
// packed silu: hv = 0.5*v (half2); silu(v) = hv*(1+tanh(hv)) = hfma2(hv, t, hv)
__device__ __forceinline__ u32 silu_from_half(u32 hv) {
    u32 th = h2tanh(hv);
    __half2 r = __hfma2(*reinterpret_cast<__half2*>(&hv),
                        *reinterpret_cast<__half2*>(&th),
                        *reinterpret_cast<__half2*>(&hv));
    return *reinterpret_cast<u32*>(&r);
}
// hv = 0.5*pack(c0,c1) + prepacked 0.5*bias
__device__ __forceinline__ u32 half_bias(float c0, float c1, u32 bp) {
    const u32 h05 = 0x38003800u;
    u32 pc = pack_h2(c0, c1);
    __half2 r = __hfma2(*reinterpret_cast<__half2*>(&pc),
                        *reinterpret_cast<const __half2*>(&h05),
                        *reinterpret_cast<__half2*>(&bp));
    return *reinterpret_cast<u32*>(&r);
}
__device__ __forceinline__ void wsplit2(float v0, float v1, u32& hw, u32& lw) {
    float h0 = __half2float(__float2half_rn(v0));
    float h1 = __half2float(__float2half_rn(v1));
    hw = pack_h2(h0, h1);
    lw = pack_h2(v0 - h0, v1 - h1);
}

#define MMA(Cb, A0, A1, A2, A3, B0, B1)                                  \
    asm volatile("mma.sync.aligned.m16n8k16.row.col.f32.f16.f16.f32 "    \
                 "{%0,%1,%2,%3}, {%4,%5,%6,%7}, {%8,%9}, {%0,%1,%2,%3};" \
                 : "+f"(Cb[0]), "+f"(Cb[1]), "+f"(Cb[2]), "+f"(Cb[3])    \
                 : "r"(A0), "r"(A1), "r"(A2), "r"(A3), "r"(B0), "r"(B1))

#define MMA8(Cb, A0, A1, B0)                                             \
    asm volatile("mma.sync.aligned.m16n8k8.row.col.f32.f16.f16.f32 "     \
                 "{%0,%1,%2,%3}, {%4,%5}, {%6}, {%0,%1,%2,%3};"          \
                 : "+f"(Cb[0]), "+f"(Cb[1]), "+f"(Cb[2]), "+f"(Cb[3])    \
                 : "r"(A0), "r"(A1), "r"(B0))

__global__ __launch_bounds__(BLK, 4)
void atomic_mlp_mma7(const float* __restrict__ desc,
                     const int*   __restrict__ numbers,
                     const float* __restrict__ W1, const float* __restrict__ b1,
                     const float* __restrict__ W2, const float* __restrict__ b2,
                     const float* __restrict__ W3, const float* __restrict__ b3,
                     float* __restrict__ out)
{
    __shared__ __align__(16) u32 sB1[56 * S1I];        // 10752 B (hi/lo interleaved)
    __shared__ __align__(16) u32 sB2[56 * S2I];        // 17920 B
    __shared__ float sraw[D_IN * H + H * H];           // 17800 B
    __shared__ u32 b1p[28], b2p[28];                   // 0.5*bias packed half2 per col-pair
    __shared__ float w3v[56];
    __shared__ float b3s;

    const int t   = threadIdx.x;
    const int wid = t >> 5;
    const int lid = t & 31;
    const int g   = lid >> 2;
    const int tq  = lid & 3;
    const int a   = blockIdx.x;
    const int s   = numbers[a];
    const int shift = a & 1;               // K-permutation: col = (k + shift) % 39

    const size_t rs   = (size_t)A_TOT * D_IN;
    const size_t acol = (size_t)a * D_IN;

    // ---- stage raw weights (coalesced, once per block) ----
    #pragma unroll
    for (int j = 0; j < 16; j++) {
        int i = t + j * BLK;
        if (i < D_IN * H) sraw[i] = W1[s * D_IN * H + i];
    }
    #pragma unroll
    for (int j = 0; j < 20; j++) {
        int i = t + j * BLK;
        if (i < H * H) sraw[D_IN * H + i] = W2[s * H * H + i];
    }
    if (t < 28) {
        int c0 = 2 * t, c1 = 2 * t + 1;
        float v0 = (c0 < H) ? 0.5f * b1[s * H + c0] : 0.0f;
        float v1 = (c1 < H) ? 0.5f * b1[s * H + c1] : 0.0f;
        b1p[t] = pack_h2(v0, v1);
        v0 = (c0 < H) ? 0.5f * b2[s * H + c0] : 0.0f;
        v1 = (c1 < H) ? 0.5f * b2[s * H + c1] : 0.0f;
        b2p[t] = pack_h2(v0, v1);
    }
    if (t >= 64 && t < 120) {
        int c = t - 64;
        w3v[c] = (c < H) ? W3[s * H + c] : 0.0f;
    }
    if (t == 0) b3s = b3[s];

    // ---- prefetch tile 0's A fragments via LDG.64 (K-permuted) ----
    u32 ahn1[2][2][4];   // kk=0,1 full k16
    u32 ahn2[2][2];      // kk=2 k8 (K 32..39)
    {
        const int R0 = (blockIdx.y * TPB) * 128 + wid * 32;
        #pragma unroll
        for (int q = 0; q < 4; q++) {
            int r = R0 + (q >> 1) * 16 + (q & 1) * 8 + g;
            const float* rp = desc + (size_t)r * rs + acol;
            const float2* rp2 = reinterpret_cast<const float2*>(rp + shift);  // 8B-aligned
            int m = q >> 1, o = q & 1;
            float2 v0 = rp2[tq];
            float2 v1 = rp2[tq + 4];
            float2 v2 = rp2[tq + 8];
            float2 v3 = rp2[tq + 12];
            float2 v4 = (tq < 3) ? rp2[tq + 16]
                                 : make_float2(rp[shift ? 0 : 38], 0.0f);
            ahn1[0][m][o]     = pack_h2(v0.x, v0.y);
            ahn1[0][m][2 + o] = pack_h2(v1.x, v1.y);
            ahn1[1][m][o]     = pack_h2(v2.x, v2.y);
            ahn1[1][m][2 + o] = pack_h2(v3.x, v3.y);
            ahn2[m][o]        = pack_h2(v4.x, v4.y);
        }
    }
    __syncthreads();

    // ---- build split-transposed, interleaved weight tiles ----
    // B1 uses the same K-permutation as the A loads: col(k) = (k + shift) % 39
    #pragma unroll
    for (int j = 0; j < 11; j++) {
        int i = t + j * BLK;
        if (i < 56 * 24) {
            int n = i / 24, w = i % 24, k0 = 2 * w;
            int c0 = k0 + shift;     if (c0 >= D_IN) c0 = 0;
            int c1 = k0 + 1 + shift; if (c1 >= D_IN) c1 = 0;
            float v0 = (k0     < D_IN && n < H) ? sraw[c0 * H + n] : 0.0f;
            float v1 = (k0 + 1 < D_IN && n < H) ? sraw[c1 * H + n] : 0.0f;
            u32 hw, lw; wsplit2(v0, v1, hw, lw);
            int kk = w >> 3, jj = w & 7;
            int p = n * S1I + kk * 16 + (jj & 3) * 4 + (jj >> 2);
            sB1[p]     = hw;
            sB1[p + 2] = lw;
        }
    }
    #pragma unroll
    for (int j = 0; j < 14; j++) {
        int i = t + j * BLK;               // exactly 56*32
        int n = i / 32, w = i % 32, k0 = 2 * w;
        float v0 = (k0     < H && n < H) ? sraw[D_IN * H + k0 * H + n]       : 0.0f;
        float v1 = (k0 + 1 < H && n < H) ? sraw[D_IN * H + (k0 + 1) * H + n] : 0.0f;
        u32 hw, lw; wsplit2(v0, v1, hw, lw);
        int kk = w >> 3, jj = w & 7;
        int p = n * S2I + kk * 16 + (jj & 3) * 4 + (jj >> 2);
        sB2[p]     = hw;
        sB2[p + 2] = lw;
    }
    __syncthreads();

    // ================= tile loop (barrier-free body) =================
    #pragma unroll 1
    for (int it = 0; it < TPB; it++) {
        u32 ah1[2][2][4], ah2[2][2];
        #pragma unroll
        for (int kk = 0; kk < 2; kk++)
            #pragma unroll
            for (int m = 0; m < 2; m++)
                #pragma unroll
                for (int o = 0; o < 4; o++)
                    ah1[kk][m][o] = ahn1[kk][m][o];
        #pragma unroll
        for (int m = 0; m < 2; m++) {
            ah2[m][0] = ahn2[m][0];
            ah2[m][1] = ahn2[m][1];
        }

        // ---- layer 1: kk=0,1 k16; kk=2 k8 ----
        float c[56];
        #pragma unroll
        for (int i = 0; i < 56; i++) c[i] = 0.0f;

        #pragma unroll
        for (int kk = 0; kk < 2; kk++)
            #pragma unroll
            for (int n = 0; n < 7; n++) {
                const uint4 b = *reinterpret_cast<const uint4*>(
                    &sB1[(n * 8 + g) * S1I + kk * 16 + 4 * tq]);
                #pragma unroll
                for (int m = 0; m < 2; m++) {
                    float* C = &c[(m * 7 + n) * 4];
                    MMA(C, ah1[kk][m][0], ah1[kk][m][1], ah1[kk][m][2], ah1[kk][m][3], b.x, b.y);
                    MMA(C, ah1[kk][m][0], ah1[kk][m][1], ah1[kk][m][2], ah1[kk][m][3], b.z, b.w);
                }
            }
        #pragma unroll
        for (int n = 0; n < 7; n++) {
            int p = (n * 8 + g) * S1I + 32 + 4 * tq;
            u32 bh = sB1[p], bl = sB1[p + 2];
            #pragma unroll
            for (int m = 0; m < 2; m++) {
                float* C = &c[(m * 7 + n) * 4];
                MMA8(C, ah2[m][0], ah2[m][1], bh);
                MMA8(C, ah2[m][0], ah2[m][1], bl);
            }
        }

        // ---- epilogue 1: packed bias + tanh-silu -> fp16 A2 frags ----
        u32 ch0[14], ch1[14];
        #pragma unroll
        for (int m = 0; m < 2; m++)
            #pragma unroll
            for (int n = 0; n < 7; n++) {
                u32 bp = b1p[n * 4 + tq];
                int idx = (m * 7 + n) * 4;
                ch0[m * 7 + n] = silu_from_half(half_bias(c[idx],     c[idx + 1], bp));
                ch1[m * 7 + n] = silu_from_half(half_bias(c[idx + 2], c[idx + 3], bp));
            }

        // ---- prefetch next tile's A (hidden behind layer-2 MMAs) ----
        if (it + 1 < TPB) {
            const int R0n = (blockIdx.y * TPB + it + 1) * 128 + wid * 32;
            #pragma unroll
            for (int q = 0; q < 4; q++) {
                int r = R0n + (q >> 1) * 16 + (q & 1) * 8 + g;
                const float* rp = desc + (size_t)r * rs + acol;
                const float2* rp2 = reinterpret_cast<const float2*>(rp + shift);
                int m = q >> 1, o = q & 1;
                float2 v0 = rp2[tq];
                float2 v1 = rp2[tq + 4];
                float2 v2 = rp2[tq + 8];
                float2 v3 = rp2[tq + 12];
                float2 v4 = (tq < 3) ? rp2[tq + 16]
                                     : make_float2(rp[shift ? 0 : 38], 0.0f);
                ahn1[0][m][o]     = pack_h2(v0.x, v0.y);
                ahn1[0][m][2 + o] = pack_h2(v1.x, v1.y);
                ahn1[1][m][o]     = pack_h2(v2.x, v2.y);
                ahn1[1][m][2 + o] = pack_h2(v3.x, v3.y);
                ahn2[m][o]        = pack_h2(v4.x, v4.y);
            }
        }

        // ---- layer 2: kk=0..2 k16; kk=3 k8 ----
        float c2[56];
        #pragma unroll
        for (int i = 0; i < 56; i++) c2[i] = 0.0f;

        #pragma unroll
        for (int kk = 0; kk < 3; kk++) {
            #pragma unroll
            for (int n = 0; n < 7; n++) {
                const uint4 b = *reinterpret_cast<const uint4*>(
                    &sB2[(n * 8 + g) * S2I + kk * 16 + 4 * tq]);
                #pragma unroll
                for (int m = 0; m < 2; m++) {
                    float* C = &c2[(m * 7 + n) * 4];
                    MMA(C, ch0[m * 7 + 2 * kk], ch1[m * 7 + 2 * kk],
                           ch0[m * 7 + 2 * kk + 1], ch1[m * 7 + 2 * kk + 1], b.x, b.y);
                    MMA(C, ch0[m * 7 + 2 * kk], ch1[m * 7 + 2 * kk],
                           ch0[m * 7 + 2 * kk + 1], ch1[m * 7 + 2 * kk + 1], b.z, b.w);
                }
            }
        }
        #pragma unroll
        for (int n = 0; n < 7; n++) {
            int p = (n * 8 + g) * S2I + 48 + 4 * tq;
            u32 bh = sB2[p], bl = sB2[p + 2];
            #pragma unroll
            for (int m = 0; m < 2; m++) {
                float* C = &c2[(m * 7 + n) * 4];
                MMA8(C, ch0[m * 7 + 6], ch1[m * 7 + 6], bh);
                MMA8(C, ch0[m * 7 + 6], ch1[m * 7 + 6], bl);
            }
        }

        // ---- epilogue 2: packed silu, fp32 dot W3, reduce, store ----
        float sum[4] = {0.0f, 0.0f, 0.0f, 0.0f};
        #pragma unroll
        for (int m = 0; m < 2; m++)
            #pragma unroll
            for (int n = 0; n < 7; n++) {
                u32 bp = b2p[n * 4 + tq];
                int col = n * 8 + 2 * tq;
                float w30 = w3v[col], w31 = w3v[col + 1];
                int idx = (m * 7 + n) * 4;
                u32 s0 = silu_from_half(half_bias(c2[idx],     c2[idx + 1], bp));
                u32 s1 = silu_from_half(half_bias(c2[idx + 2], c2[idx + 3], bp));
                float2 F0 = __half22float2(*reinterpret_cast<__half2*>(&s0));
                float2 F1 = __half22float2(*reinterpret_cast<__half2*>(&s1));
                sum[m * 2 + 0] += F0.x * w30 + F0.y * w31;
                sum[m * 2 + 1] += F1.x * w30 + F1.y * w31;
            }
        #pragma unroll
        for (int q = 0; q < 4; q++) {
            sum[q] += __shfl_xor_sync(0xffffffffu, sum[q], 1);
            sum[q] += __shfl_xor_sync(0xffffffffu, sum[q], 2);
        }
        if (tq == 0) {
            const int R0 = (blockIdx.y * TPB + it) * 128 + wid * 32;
            float bb = b3s;
            #pragma unroll
            for (int q = 0; q < 4; q++) {
                int r = R0 + (q >> 1) * 16 + (q & 1) * 8 + g;
                out[(size_t)r * A_TOT + a] = sum[q] + bb;
            }
        }
    }
}

extern "C" void kernel_launch(void* const* d_in, const int* in_sizes, int n_in,
                              void* d_out, int out_size)
{
    const float* desc    = (const float*)d_in[0];
    const int*   numbers = (const int*)  d_in[1];
    const float* W1      = (const float*)d_in[2];
    const float* b1      = (const float*)d_in[3];
    const float* W2      = (const float*)d_in[4];
    const float* b2      = (const float*)d_in[5];
    const float* W3      = (const float*)d_in[6];
    const float* b3      = (const float*)d_in[7];
    float* out = (float*)d_out;

    const int N = in_sizes[0] / (A_TOT * D_IN);   // 4096
    dim3 grid(A_TOT, N / (128 * TPB));            // 256 x 8
    atomic_mlp_mma7<<<grid, BLK>>>(desc, numbers, W1, b1, W2, b2, W3, b3, out);
}